// round 8
// baseline (speedup 1.0000x reference)
#include <cuda_runtime.h>
#include <cooperative_groups.h>
#include <cstdint>

namespace cg = cooperative_groups;

// Problem constants
#define T_DIM 1024
#define N_DIM 32
#define CI    512
#define CO    512

// Scan decomposition
#define CSIZE  4               // CTAs per cluster (one cluster per batch)
#define PSLICE 128             // neurons per CTA
#define ROWS_S 416             // RT rows cached in smem; rows >=416 from L2/L1
#define NTHR   512             // 4 slot-groups x 128 neuron columns

// Scratch (allocation-free rule: __device__ globals)
__device__ float g_z[T_DIM * N_DIM * CO];   // [t][n][o]
__device__ float g_RT[CO * CO];             // RT[o][p] = R[p][o]

// ---------------------------------------------------------------------------
// Kernel 1: transpose R -> RT.
// ---------------------------------------------------------------------------
__global__ void transpose_R_kernel(const float* __restrict__ R) {
    int idx = blockIdx.x * blockDim.x + threadIdx.x;   // idx = o*CO + p
    int o = idx >> 9;
    int p = idx & 511;
    g_RT[idx] = R[p * CO + o];
}

// ---------------------------------------------------------------------------
// Kernel 2: z[t][n][o] = sum_c x[n][c][t] * W[o][c]
// 128x128 tile, 8x8 micro, double-buffered smem. Per-output accumulation is
// a single register, k ascending 0..511 -> bit-identical to R1's z.
// ---------------------------------------------------------------------------
#define GBM 128
#define GBN 128
#define GBK 16
#define GNIT (CI / GBK)          // 32
#define WSP (GBN + 4)            // 132 floats: pad, keeps 16B alignment

__global__ __launch_bounds__(256, 2) void gemm_z_kernel(
    const float* __restrict__ x, const float* __restrict__ W)
{
    __shared__ __align__(16) float xs[2][GBK][GBM];
    __shared__ __align__(16) float ws[2][GBK][WSP];

    const int n  = blockIdx.z;
    const int t0 = blockIdx.x * GBM;
    const int o0 = blockIdx.y * GBN;
    const int tid = threadIdx.x;
    const int tx = tid & 15;    // o micro (8 outputs)
    const int ty = tid >> 4;    // t micro (8 outputs)

    float acc[8][8];
#pragma unroll
    for (int i = 0; i < 8; ++i)
#pragma unroll
        for (int j = 0; j < 8; ++j) acc[i][j] = 0.f;

    const float* xbase = x + (size_t)n * CI * T_DIM + t0;

    float rx[8], rw[8];
    // preload tile 0 into regs
#pragma unroll
    for (int it = 0; it < 8; ++it) {
        int idx = tid + it * 256;
        rx[it] = xbase[(idx >> 7) * T_DIM + (idx & 127)];
        rw[it] = W[(o0 + (idx >> 4)) * CI + (idx & 15)];
    }
#pragma unroll
    for (int it = 0; it < 8; ++it) {
        int idx = tid + it * 256;
        xs[0][idx >> 7][idx & 127] = rx[it];
        ws[0][idx & 15][idx >> 4]  = rw[it];
    }
    __syncthreads();

    for (int i = 0; i < GNIT; ++i) {
        const int cur = i & 1;
        if (i + 1 < GNIT) {
            const int c0 = (i + 1) * GBK;
#pragma unroll
            for (int it = 0; it < 8; ++it) {
                int idx = tid + it * 256;
                rx[it] = xbase[(c0 + (idx >> 7)) * T_DIM + (idx & 127)];
                rw[it] = W[(o0 + (idx >> 4)) * CI + c0 + (idx & 15)];
            }
        }
#pragma unroll
        for (int k = 0; k < GBK; ++k) {
            float4 a0 = *(const float4*)&xs[cur][k][ty * 8];
            float4 a1 = *(const float4*)&xs[cur][k][ty * 8 + 4];
            float4 b0 = *(const float4*)&ws[cur][k][tx * 8];
            float4 b1 = *(const float4*)&ws[cur][k][tx * 8 + 4];
            float a[8] = {a0.x, a0.y, a0.z, a0.w, a1.x, a1.y, a1.z, a1.w};
            float b[8] = {b0.x, b0.y, b0.z, b0.w, b1.x, b1.y, b1.z, b1.w};
#pragma unroll
            for (int ii = 0; ii < 8; ++ii)
#pragma unroll
                for (int jj = 0; jj < 8; ++jj)
                    acc[ii][jj] += a[ii] * b[jj];
        }
        if (i + 1 < GNIT) {
            const int nxt = cur ^ 1;
#pragma unroll
            for (int it = 0; it < 8; ++it) {
                int idx = tid + it * 256;
                xs[nxt][idx >> 7][idx & 127] = rx[it];
                ws[nxt][idx & 15][idx >> 4]  = rw[it];
            }
            __syncthreads();
        }
    }

#pragma unroll
    for (int i = 0; i < 8; ++i) {
        int t = t0 + ty * 8 + i;
        float* dst = &g_z[((size_t)t * N_DIM + n) * CO + o0 + tx * 8];
        *(float4*)dst       = make_float4(acc[i][0], acc[i][1], acc[i][2], acc[i][3]);
        *(float4*)(dst + 4) = make_float4(acc[i][4], acc[i][5], acc[i][6], acc[i][7]);
    }
}

// ---------------------------------------------------------------------------
// Kernel 3: cluster-parallel LIF scan, slot-parallel gather.
// Bit-exact accumulation order (R1/R4..R7). This round: cluster.sync in the
// loop replaced by a parity double-buffered mbarrier exchange (count=16:
// 4 source CTAs x 4 warps each push one mask word + remote release arrive).
// ---------------------------------------------------------------------------
#define RTS_ROWS    (ROWS_S + 1)
#define RTS_ELEMS   (RTS_ROWS * PSLICE)
#define STAGE_ELEMS (PSLICE * 17)
// layout: RTs | stage | comb[3*128] | masks[2][16] | mbars[2] | lists | tail
#define SMEM_BYTES  (RTS_ELEMS * 4 + STAGE_ELEMS * 4 + 3 * PSLICE * 4 \
                     + 32 * 4 + 16 + 4 * 128 * 2 + 8 * 2)

extern __shared__ float smem_dyn[];

__device__ __forceinline__ unsigned smem_u32(const void* ptr) {
    unsigned a;
    asm("{ .reg .u64 t; cvta.to.shared.u64 t, %1; cvt.u32.u64 %0, t; }"
        : "=r"(a) : "l"(ptr));
    return a;
}

__device__ __forceinline__ void mbar_init(unsigned addr, unsigned count) {
    asm volatile("mbarrier.init.shared.b64 [%0], %1;"
                 :: "r"(addr), "r"(count) : "memory");
}

// Store mask word into CTA `rk`'s smem and arrive on its mbarrier (release).
__device__ __forceinline__ void mask_send(unsigned mask_addr, unsigned bal,
                                          unsigned rk, unsigned mbar_addr) {
    asm volatile(
        "{\n\t"
        ".reg .b32 rm, rb;\n\t"
        "mapa.shared::cluster.u32 rm, %0, %2;\n\t"
        "st.shared::cluster.u32 [rm], %1;\n\t"
        "mapa.shared::cluster.u32 rb, %3, %2;\n\t"
        "mbarrier.arrive.release.cluster.shared::cluster.b64 _, [rb];\n\t"
        "}"
        :: "r"(mask_addr), "r"(bal), "r"(rk), "r"(mbar_addr) : "memory");
}

__device__ __forceinline__ void mbar_wait(unsigned addr, unsigned parity) {
    asm volatile(
        "{\n\t"
        ".reg .pred P;\n\t"
        "WAIT_%=:\n\t"
        "mbarrier.try_wait.parity.acquire.cluster.shared::cta.b64 P, [%0], %1;\n\t"
        "@P bra DONE_%=;\n\t"
        "bra WAIT_%=;\n\t"
        "DONE_%=:\n\t"
        "}"
        :: "r"(addr), "r"(parity) : "memory");
}

// Load 8 rows of this thread's column, given 8 packed int16 indices.
// Index -1 (padding sentinel) maps to the smem zero row.
__device__ __forceinline__ void load8(const int4* __restrict__ l4, int b,
                                      const float* __restrict__ RTc,
                                      const float* __restrict__ gcol,
                                      float dst[8])
{
    int4 w = l4[b];
    int o;
    o = (int)(short)(w.x & 0xffff);
    dst[0] = (o < ROWS_S) ? RTc[(o + 1) * PSLICE] : __ldg(&gcol[o * CO]);
    o = (int)(short)(w.x >> 16);
    dst[1] = (o < ROWS_S) ? RTc[(o + 1) * PSLICE] : __ldg(&gcol[o * CO]);
    o = (int)(short)(w.y & 0xffff);
    dst[2] = (o < ROWS_S) ? RTc[(o + 1) * PSLICE] : __ldg(&gcol[o * CO]);
    o = (int)(short)(w.y >> 16);
    dst[3] = (o < ROWS_S) ? RTc[(o + 1) * PSLICE] : __ldg(&gcol[o * CO]);
    o = (int)(short)(w.z & 0xffff);
    dst[4] = (o < ROWS_S) ? RTc[(o + 1) * PSLICE] : __ldg(&gcol[o * CO]);
    o = (int)(short)(w.z >> 16);
    dst[5] = (o < ROWS_S) ? RTc[(o + 1) * PSLICE] : __ldg(&gcol[o * CO]);
    o = (int)(short)(w.w & 0xffff);
    dst[6] = (o < ROWS_S) ? RTc[(o + 1) * PSLICE] : __ldg(&gcol[o * CO]);
    o = (int)(short)(w.w >> 16);
    dst[7] = (o < ROWS_S) ? RTc[(o + 1) * PSLICE] : __ldg(&gcol[o * CO]);
}

__global__ void __cluster_dims__(CSIZE, 1, 1) __launch_bounds__(NTHR, 1)
scan_kernel(float* __restrict__ out)
{
    float*    RTs   = smem_dyn;                              // [417][128]
    float*    stage = RTs + RTS_ELEMS;                       // [128][17]
    float*    comb  = stage + STAGE_ELEMS;                   // [3][128]
    unsigned* masks = (unsigned*)(comb + 3 * PSLICE);        // [2][16]
    unsigned long long* mbars = (unsigned long long*)(masks + 32);  // [2]
    short*    lists = (short*)(mbars + 2);                   // [4][128]
    short*    tail  = lists + 4 * 128;                       // [8]

    cg::cluster_group cluster = cg::this_cluster();
    const int rank = (int)cluster.block_rank();
    const int n    = blockIdx.x / CSIZE;

    const int tid  = threadIdx.x;
    const int warp = tid >> 5;
    const int lane = tid & 31;
    const int slot = tid >> 7;              // 0..3 accumulator slot
    const int col  = tid & 127;             // neuron column within slice
    const int p    = rank * PSLICE + col;   // global neuron (column in g_RT)

    const unsigned masks_base = smem_u32(masks);
    const unsigned mbar_base  = smem_u32(mbars);

    // RT slice: smem row 0 = zeros, rows 1..416 = g_RT rows 0..415.
    RTs[col] = 0.f;
    for (int o = slot; o < ROWS_S; o += 4)
        RTs[(o + 1) * PSLICE + col] = g_RT[o * CO + p];

    float cur = 0.f, v = 0.f, s = 0.f;
    if (slot == 0) stage[col * 17 + 0] = 0.f;   // delay shift: out[...,0]=0

    if (tid == 0) {
        mbar_init(mbar_base, 16);       // parity 0 barrier
        mbar_init(mbar_base + 8, 16);   // parity 1 barrier
    }
    __syncthreads();
    cluster.sync();   // mbarrier init + RTs visible before any remote arrive

    const float* RTc  = RTs + col;
    const float* gcol = g_RT + p;
    const int4*  l4   = (const int4*)(lists + slot * 128);

    for (int t = 0; t < T_DIM - 1; ++t) {
        const int      par = t & 1;
        const unsigned ph  = (t >> 1) & 1;
        float zv = 0.f;

        if (slot == 0) {
            zv = g_z[((size_t)t * N_DIM + n) * CO + p];   // hidden under wait
            unsigned bal = __ballot_sync(0xffffffffu, s > 0.5f);
            if (lane < CSIZE) {
                mask_send(masks_base + (par * 16 + rank * 4 + warp) * 4,
                          bal, (unsigned)lane, mbar_base + par * 8);
            }
        }
        mbar_wait(mbar_base + par * 8, ph);   // all 16 mask words arrived

        // ---- parallel list build: thread tid handles candidate o = tid ----
        const unsigned* mw = masks + par * 16;
        unsigned myw = mw[warp];
        int cw = (lane < 16) ? __popc(mw[lane]) : 0;
        int inc = cw;
#pragma unroll
        for (int d = 1; d < 16; d <<= 1) {
            int u = __shfl_up_sync(0xffffffffu, inc, d);
            if (lane >= d) inc += u;
        }
        const int tot   = __shfl_sync(0xffffffffu, inc, 15);
        const int exc_w = (warp == 0) ? 0
                          : __shfl_sync(0xffffffffu, inc, warp - 1);
        const int M4 = tot & ~3;

        if ((myw >> lane) & 1u) {
            int rk = exc_w + __popc(myw & ((1u << lane) - 1u));
            if (rk < M4) lists[(rk & 3) * 128 + (rk >> 2)] = (short)tid;
            else         tail[rk - M4] = (short)tid;
        }
        const int cnt     = M4 >> 2;
        const int cnt_pad = (cnt + 7) & ~7;
        if (tid < 32) {
            int k = tid >> 3, j = tid & 7;
            if (cnt + j < cnt_pad) lists[k * 128 + cnt + j] = (short)(-1);
        }
        __syncthreads();

        const int nblk = cnt_pad >> 3;

        // ---- slot gather: tail blocks first, pipelined smem blocks ----
        float acc = 0.f;
        if (nblk >= 3) {
            float T[16];
            load8(l4, nblk - 2, RTc, gcol, T);
            load8(l4, nblk - 1, RTc, gcol, T + 8);

            float A[8], B[8];
            load8(l4, 0, RTc, gcol, A);
            const int nb = nblk - 2;
            for (int b = 0; b < nb; b += 2) {
                if (b + 1 < nb) load8(l4, b + 1, RTc, gcol, B);
#pragma unroll
                for (int u = 0; u < 8; ++u) acc += A[u];
                if (b + 2 < nb) load8(l4, b + 2, RTc, gcol, A);
                if (b + 1 < nb) {
#pragma unroll
                    for (int u = 0; u < 8; ++u) acc += B[u];
                }
            }
#pragma unroll
            for (int u = 0; u < 16; ++u) acc += T[u];
        } else if (nblk > 0) {
            float T[8];
            for (int b = 0; b < nblk; ++b) {
                load8(l4, b, RTc, gcol, T);
#pragma unroll
                for (int u = 0; u < 8; ++u) acc += T[u];
            }
        }
        // slot 0 adds the <4 tail rows (positions M4..tot-1), in order
        if (slot == 0 && M4 < tot) {
            int rem = tot - M4;
            int o0 = tail[0];
            float r0 = (o0 < ROWS_S) ? RTc[(o0 + 1) * PSLICE] : __ldg(&gcol[o0 * CO]);
            float r1 = 0.f, r2 = 0.f;
            if (rem > 1) { int o1 = tail[1];
                r1 = (o1 < ROWS_S) ? RTc[(o1 + 1) * PSLICE] : __ldg(&gcol[o1 * CO]); }
            if (rem > 2) { int o2 = tail[2];
                r2 = (o2 < ROWS_S) ? RTc[(o2 + 1) * PSLICE] : __ldg(&gcol[o2 * CO]); }
            acc += r0; acc += r1; acc += r2;     // +0.0f is bit-exact identity
        }

        // ---- combine slots (rec = zv + ((a0+a1)+(a2+a3))) ----
        if (slot != 0) comb[(slot - 1) * PSLICE + col] = acc;
        __syncthreads();

        if (slot == 0) {
            float a1 = comb[col];
            float a2 = comb[PSLICE + col];
            float a3 = comb[2 * PSLICE + col];
            float rec = zv + ((acc + a1) + (a2 + a3));

            cur = 0.75f * cur + rec;
            v   = 0.9f * v * (1.f - s) + cur;
            float s_new = (v >= 1.0f) ? 1.f : 0.f;
            s = s_new;

            stage[col * 17 + ((t + 1) & 15)] = s_new;
        }

        // ---- flush stage every 16 steps, coalesced, all 512 threads ----
        if (((t + 1) & 15) == 15) {
            __syncthreads();
            const int qbase = (t + 1) & ~15;
#pragma unroll
            for (int it = 0; it < 4; ++it) {
                int vidx = it * NTHR + tid;
                int pp = vidx >> 4;
                int tt = vidx & 15;
                out[((size_t)n * CO + rank * PSLICE + pp) * T_DIM + qbase + tt] =
                    stage[pp * 17 + tt];
            }
            __syncthreads();   // stage reuse guard (no cluster.sync anymore)
        }
    }
}

// ---------------------------------------------------------------------------
// Launch
// ---------------------------------------------------------------------------
extern "C" void kernel_launch(void* const* d_in, const int* in_sizes, int n_in,
                              void* d_out, int out_size)
{
    const float* x = (const float*)d_in[0];   // [32, 512, 1024]
    const float* W = (const float*)d_in[1];   // [512, 512]
    const float* R = (const float*)d_in[2];   // [512, 512]
    float* out = (float*)d_out;               // [32, 512, 1024]

    cudaFuncSetAttribute(scan_kernel,
                         cudaFuncAttributeMaxDynamicSharedMemorySize,
                         SMEM_BYTES);

    transpose_R_kernel<<<(CO * CO) / 256, 256>>>(R);

    dim3 ggrid(T_DIM / GBM, CO / GBN, N_DIM);
    gemm_z_kernel<<<ggrid, 256>>>(x, W);

    scan_kernel<<<N_DIM * CSIZE, NTHR, SMEM_BYTES>>>(out);
}

// round 9
// speedup vs baseline: 1.2061x; 1.2061x over previous
#include <cuda_runtime.h>
#include <cooperative_groups.h>
#include <cstdint>

namespace cg = cooperative_groups;

// Problem constants
#define T_DIM 1024
#define N_DIM 32
#define CI    512
#define CO    512

// Scan decomposition
#define CSIZE  4               // CTAs per cluster (one cluster per batch)
#define PSLICE 128             // neurons per CTA
#define ROWS_S 416             // RT rows cached in smem; rows >=416 from L2/L1
#define NTHR   512             // 4 slot-groups x 128 neuron columns
#define SLOTW  112             // smem list capacity per slot (ints, padded)
#define GLOTW  32              // gmem list capacity per slot (ints, padded)

// Scratch (allocation-free rule: __device__ globals).
// g_RT has one extra zero row (index CO) used as the gmem padding sentinel.
__device__ float g_z[T_DIM * N_DIM * CO];   // [t][n][o]
__device__ float g_RT[(CO + 1) * CO];       // RT[o][p] = R[p][o]; row CO = 0

// ---------------------------------------------------------------------------
// Kernel 1: transpose R -> RT (plus zero sentinel row CO).
// ---------------------------------------------------------------------------
__global__ void transpose_R_kernel(const float* __restrict__ R) {
    int idx = blockIdx.x * blockDim.x + threadIdx.x;   // < (CO+1)*CO
    int o = idx >> 9;
    int p = idx & 511;
    g_RT[idx] = (o < CO) ? R[p * CO + o] : 0.f;
}

// ---------------------------------------------------------------------------
// Kernel 2: z GEMM — verbatim R7 (proven numerics + proven perf).
// ---------------------------------------------------------------------------
#define BM 128
#define BN 64
#define BK 16
#define WS_STRIDE 68

__global__ __launch_bounds__(256) void gemm_z_kernel(
    const float* __restrict__ x, const float* __restrict__ W)
{
    __shared__ float xs[BK][BM];
    __shared__ float ws[BK][WS_STRIDE];

    const int n  = blockIdx.z;
    const int t0 = blockIdx.x * BM;
    const int o0 = blockIdx.y * BN;
    const int tid = threadIdx.x;
    const int tx = tid & 15;
    const int ty = tid >> 4;

    float acc[8][4];
#pragma unroll
    for (int i = 0; i < 8; ++i)
#pragma unroll
        for (int j = 0; j < 4; ++j) acc[i][j] = 0.f;

    const float* xbase = x + (size_t)n * CI * T_DIM + t0;

    for (int c0 = 0; c0 < CI; c0 += BK) {
#pragma unroll
        for (int it = 0; it < 8; ++it) {
            int idx = tid + it * 256;
            int cc = idx >> 7;
            int tt = idx & 127;
            xs[cc][tt] = xbase[(c0 + cc) * T_DIM + tt];
        }
#pragma unroll
        for (int it = 0; it < 4; ++it) {
            int idx = tid + it * 256;
            int oo = idx >> 4;
            int cc = idx & 15;
            ws[cc][oo] = W[(o0 + oo) * CI + (c0 + cc)];
        }
        __syncthreads();

#pragma unroll
        for (int k = 0; k < BK; ++k) {
            float a[8], b[4];
#pragma unroll
            for (int i = 0; i < 8; ++i) a[i] = xs[k][ty * 8 + i];
#pragma unroll
            for (int j = 0; j < 4; ++j) b[j] = ws[k][tx * 4 + j];
#pragma unroll
            for (int i = 0; i < 8; ++i)
#pragma unroll
                for (int j = 0; j < 4; ++j)
                    acc[i][j] += a[i] * b[j];
        }
        __syncthreads();
    }

#pragma unroll
    for (int i = 0; i < 8; ++i) {
        int t = t0 + ty * 8 + i;
        float4 v4 = make_float4(acc[i][0], acc[i][1], acc[i][2], acc[i][3]);
        *(float4*)&g_z[((size_t)t * N_DIM + n) * CO + o0 + tx * 4] = v4;
    }
}

// ---------------------------------------------------------------------------
// Kernel 3: cluster-parallel LIF scan — R7 structure (cluster.sync exchange),
// with split-list gather:
//   lists_s[slot][]: byte offsets (o+1)*512 into the smem RT slice (3 instr/row)
//   lists_g[slot][]: byte offsets o*2048 into g_RT column (prefetched to regs)
// Sorted list => smem rows precede gmem rows within each slot, so
// "smem adds then gmem adds" is EXACTLY the frozen accumulation order.
// ---------------------------------------------------------------------------
#define RTS_ROWS    (ROWS_S + 1)     // row 0 = zero sentinel
#define RTS_ELEMS   (RTS_ROWS * PSLICE)
#define STAGE_ELEMS (PSLICE * 17)
#define SMEM_BYTES  (RTS_ELEMS * 4 + STAGE_ELEMS * 4 + 3 * PSLICE * 4 \
                     + 2 * 16 * 4 + 4 * SLOTW * 4 + 4 * GLOTW * 4 + 8 * 2)

extern __shared__ float smem_dyn[];

__global__ void __cluster_dims__(CSIZE, 1, 1) __launch_bounds__(NTHR, 1)
scan_kernel(float* __restrict__ out)
{
    float*    RTs     = smem_dyn;                              // [417][128]
    float*    stage   = RTs + RTS_ELEMS;                       // [128][17]
    float*    comb    = stage + STAGE_ELEMS;                   // [3][128]
    unsigned* masks   = (unsigned*)(comb + 3 * PSLICE);        // [2][16]
    int*      lists_s = (int*)(masks + 32);                    // [4][SLOTW]
    int*      lists_g = lists_s + 4 * SLOTW;                   // [4][GLOTW]
    short*    tail    = (short*)(lists_g + 4 * GLOTW);         // [8]

    cg::cluster_group cluster = cg::this_cluster();
    const int rank = (int)cluster.block_rank();
    const int n    = blockIdx.x / CSIZE;

    const int tid  = threadIdx.x;
    const int warp = tid >> 5;
    const int lane = tid & 31;
    const int slot = tid >> 7;              // 0..3 accumulator slot
    const int col  = tid & 127;             // neuron column within slice
    const int p    = rank * PSLICE + col;   // global neuron (column in g_RT)

    // RT slice: smem row 0 = zeros, rows 1..416 = g_RT rows 0..415.
    RTs[col] = 0.f;
    for (int o = slot; o < ROWS_S; o += 4)
        RTs[(o + 1) * PSLICE + col] = g_RT[o * CO + p];

    float cur = 0.f, v = 0.f, s = 0.f;
    if (slot == 0) stage[col * 17 + 0] = 0.f;   // delay shift: out[...,0]=0

    const float*      RTc  = RTs + col;
    const char*       RTb  = (const char*)(RTs + col);   // byte base, own col
    const float*      gcol = g_RT + p;
    const char*       gb   = (const char*)(g_RT + p);

    __syncthreads();

    for (int t = 0; t < T_DIM - 1; ++t) {
        const int par = t & 1;
        float zv = 0.f;

        if (slot == 0) {
            zv = g_z[((size_t)t * N_DIM + n) * CO + p];   // hidden under sync
            unsigned bal = __ballot_sync(0xffffffffu, s > 0.5f);
            if (lane < CSIZE) {
                unsigned* dst = cluster.map_shared_rank(
                    &masks[par * 16 + rank * 4 + warp], (unsigned)lane);
                *dst = bal;
            }
        }
        cluster.sync();   // masks[par] visible everywhere; full cluster barrier

        // ---- parallel list build: thread tid handles candidate o = tid ----
        const unsigned* mw = masks + par * 16;
        unsigned myw = mw[warp];
        int cw = (lane < 16) ? __popc(mw[lane]) : 0;
        int inc = cw;
#pragma unroll
        for (int d = 1; d < 16; d <<= 1) {
            int u = __shfl_up_sync(0xffffffffu, inc, d);
            if (lane >= d) inc += u;
        }
        const int tot   = __shfl_sync(0xffffffffu, inc, 15);
        const int totS  = __shfl_sync(0xffffffffu, inc, 12);  // spikes with o<416
        const int exc_w = (warp == 0) ? 0
                          : __shfl_sync(0xffffffffu, inc, warp - 1);
        const int M4 = tot & ~3;
        const int S  = (totS < M4) ? totS : M4;   // smem-row ranks = [0, S)

        if ((myw >> lane) & 1u) {
            int rk = exc_w + __popc(myw & ((1u << lane) - 1u));
            if (rk >= M4) {
                tail[rk - M4] = (short)tid;
            } else if (tid < ROWS_S) {
                lists_s[(rk & 3) * SLOTW + (rk >> 2)] = (tid + 1) * 512;
            } else {
                int sl = rk & 3;
                int cs = (S >> 2) + (((S & 3) > sl) ? 1 : 0);
                lists_g[sl * GLOTW + (rk >> 2) - cs] = tid * 2048;
            }
        }
        // padding: smem lists to x4 (sentinel 0 = zero row), gmem to x8
        if (tid < 16) {           // 4 slots x up to 4 pads
            int sl = tid >> 2, j = tid & 3;
            int cs = (S >> 2) + (((S & 3) > sl) ? 1 : 0);
            if (cs + j < ((cs + 3) & ~3)) lists_s[sl * SLOTW + cs + j] = 0;
        } else if (tid < 48) {    // 4 slots x up to 8 pads
            int k2 = tid - 16;
            int sl = k2 >> 3, j = k2 & 7;
            int cs = (S >> 2) + (((S & 3) > sl) ? 1 : 0);
            int cg = (M4 >> 2) - cs;
            if (cg + j < ((cg + 7) & ~7))
                lists_g[sl * GLOTW + cg + j] = CO * 2048;   // zero row
        }
        __syncthreads();

        const int cs_my  = (S >> 2) + (((S & 3) > slot) ? 1 : 0);
        const int nblk_s = ((cs_my + 3) & ~3) >> 2;
        const int cg_my  = (M4 >> 2) - cs_my;
        const int nblk_g = ((cg_my + 7) & ~7) >> 3;   // <= 3

        // ---- gmem prefetch first (latency covered by smem loop) ----
        const int* lg = lists_g + slot * GLOTW;
        float G[24];
#pragma unroll
        for (int b = 0; b < 3; ++b) {
            if (b < nblk_g) {
#pragma unroll
                for (int u = 0; u < 8; ++u) {
                    int e = lg[b * 8 + u];
                    G[b * 8 + u] = __ldg((const float*)(gb + e));
                }
            } else {
#pragma unroll
                for (int u = 0; u < 8; ++u) G[b * 8 + u] = 0.f;
            }
        }

        // ---- smem gather: 3 instr/row (IADD+LDS+FADD), entry prefetch ----
        float acc = 0.f;
        const int4* ls4 = (const int4*)(lists_s + slot * SLOTW);
        if (nblk_s > 0) {
            int4 e = ls4[0];
            for (int b = 0; b < nblk_s; ++b) {
                int4 en = (b + 1 < nblk_s) ? ls4[b + 1] : e;
                acc += *(const float*)(RTb + e.x);
                acc += *(const float*)(RTb + e.y);
                acc += *(const float*)(RTb + e.z);
                acc += *(const float*)(RTb + e.w);
                e = en;
            }
        }
        // ---- gmem adds, in order, after all smem adds (sorted => exact) ----
#pragma unroll
        for (int u = 0; u < 24; ++u) acc += G[u];

        // slot 0 adds the <4 tail rows (positions M4..tot-1), in order
        if (slot == 0 && M4 < tot) {
            int rem = tot - M4;
            int o0 = tail[0];
            float r0 = (o0 < ROWS_S) ? RTc[(o0 + 1) * PSLICE] : __ldg(&gcol[o0 * CO]);
            float r1 = 0.f, r2 = 0.f;
            if (rem > 1) { int o1 = tail[1];
                r1 = (o1 < ROWS_S) ? RTc[(o1 + 1) * PSLICE] : __ldg(&gcol[o1 * CO]); }
            if (rem > 2) { int o2 = tail[2];
                r2 = (o2 < ROWS_S) ? RTc[(o2 + 1) * PSLICE] : __ldg(&gcol[o2 * CO]); }
            acc += r0; acc += r1; acc += r2;     // +0.0f is bit-exact identity
        }

        // ---- combine slots (rec = zv + ((a0+a1)+(a2+a3))) ----
        if (slot != 0) comb[(slot - 1) * PSLICE + col] = acc;
        __syncthreads();

        if (slot == 0) {
            float a1 = comb[col];
            float a2 = comb[PSLICE + col];
            float a3 = comb[2 * PSLICE + col];
            float rec = zv + ((acc + a1) + (a2 + a3));

            cur = 0.75f * cur + rec;
            v   = 0.9f * v * (1.f - s) + cur;
            float s_new = (v >= 1.0f) ? 1.f : 0.f;
            s = s_new;

            stage[col * 17 + ((t + 1) & 15)] = s_new;
        }

        // ---- flush stage every 16 steps, coalesced, all 512 threads ----
        if (((t + 1) & 15) == 15) {
            __syncthreads();
            const int qbase = (t + 1) & ~15;
#pragma unroll
            for (int it = 0; it < 4; ++it) {
                int vidx = it * NTHR + tid;
                int pp = vidx >> 4;
                int tt = vidx & 15;
                out[((size_t)n * CO + rank * PSLICE + pp) * T_DIM + qbase + tt] =
                    stage[pp * 17 + tt];
            }
        }
        // next iteration's cluster.sync orders all shared-buffer reuse
    }
}

// ---------------------------------------------------------------------------
// Launch
// ---------------------------------------------------------------------------
extern "C" void kernel_launch(void* const* d_in, const int* in_sizes, int n_in,
                              void* d_out, int out_size)
{
    const float* x = (const float*)d_in[0];   // [32, 512, 1024]
    const float* W = (const float*)d_in[1];   // [512, 512]
    const float* R = (const float*)d_in[2];   // [512, 512]
    float* out = (float*)d_out;               // [32, 512, 1024]

    cudaFuncSetAttribute(scan_kernel,
                         cudaFuncAttributeMaxDynamicSharedMemorySize,
                         SMEM_BYTES);

    transpose_R_kernel<<<((CO + 1) * CO + 255) / 256, 256>>>(R);

    dim3 ggrid(T_DIM / BM, CO / BN, N_DIM);
    gemm_z_kernel<<<ggrid, 256>>>(x, W);

    scan_kernel<<<N_DIM * CSIZE, NTHR, SMEM_BYTES>>>(out);
}